// round 4
// baseline (speedup 1.0000x reference)
#include <cuda_runtime.h>
#include <math.h>

#define BB 128
#define NN 4096
#define DD 64
#define SS 7
#define HH 128
#define NUM_ITERS 3
#define EPSV 1e-8f
#define LN_EPS 1e-5f
#define SCALE 0.125f   // 64^-0.5

#define TILE 128
#define PADF4 17       // float4 pitch per token row (68 floats)

// persistent scratch (no allocation allowed)
__device__ float g_slots[BB*SS*DD];
__device__ float g_qt[BB*SS*DD];    // qw = (ln_in_w ⊙ qt)   [b][s][64]
__device__ float g_qsc[BB*SS*2];    // {sw, sb} per (b,s)
__device__ float g_u[BB*SS*DD];     // G1 = sum_n (p*r) * x
__device__ float g_den[BB*SS];      // sum_n p
__device__ float g_c2[BB*SS];       // sum_n p*r*m
__device__ float g_M[DD*DD];        // scale * Wq^T @ Wk   [e][t]
__device__ float g_C[3*DD*DD];      // W_ih @ Wv           [j][e]

// ---------------------------------------------------------------------------
__global__ void k_init_slots(const float* __restrict__ noise,
                             const float* __restrict__ mu,
                             const float* __restrict__ logsig) {
    int i = blockIdx.x * blockDim.x + threadIdx.x;
    if (i < BB*SS*DD) {
        int d = i & 63;
        g_slots[i] = mu[d] + expf(logsig[d]) * noise[i];
    }
}

// ---------------------------------------------------------------------------
// M = scale * Wq^T @ Wk ;  C = W_ih @ Wv
__global__ void k_precomp(const float* __restrict__ Wq,
                          const float* __restrict__ Wk,
                          const float* __restrict__ W_ih,
                          const float* __restrict__ Wv) {
    int bi = blockIdx.x, t = threadIdx.x;
    if (bi < 16) {
        int o = bi*256 + t;
        int e = o >> 6, tc = o & 63;
        float acc = 0.f;
        #pragma unroll 8
        for (int d = 0; d < 64; d++)
            acc += Wq[d*64 + e] * Wk[d*64 + tc];
        g_M[e*64 + tc] = acc * SCALE;
    } else {
        int o = (bi-16)*256 + t;
        int j = o >> 6, e = o & 63;
        float acc = 0.f;
        #pragma unroll 8
        for (int h = 0; h < 64; h++)
            acc += W_ih[j*64 + h] * Wv[h*64 + e];
        g_C[j*64 + e] = acc;
    }
}

// ---------------------------------------------------------------------------
// Initial q prep: qt = LN(slots)@M ; qw = qt*w_in ; sw,sb ; zero accumulators.
__global__ void k_q0(const float* __restrict__ lnw,
                     const float* __restrict__ lnb,
                     const float* __restrict__ w_in,
                     const float* __restrict__ b_in) {
    int b = blockIdx.x;
    int tid = threadIdx.x;
    int w = tid >> 5, lane = tid & 31;
    __shared__ float sn[SS*64];
    __shared__ float qtmp[SS*64];

    if (w < SS) {
        const float* sl = g_slots + (b*SS + w)*DD;
        float v0 = sl[lane], v1 = sl[lane+32];
        float sum = v0 + v1, sq = v0*v0 + v1*v1;
        #pragma unroll
        for (int o = 16; o; o >>= 1) {
            sum += __shfl_xor_sync(0xffffffffu, sum, o);
            sq  += __shfl_xor_sync(0xffffffffu, sq,  o);
        }
        float mean = sum * (1.f/64.f);
        float var  = sq  * (1.f/64.f) - mean*mean;
        float rstd = rsqrtf(var + LN_EPS);
        sn[w*64 + lane]    = (v0 - mean)*rstd*lnw[lane]    + lnb[lane];
        sn[w*64 + lane+32] = (v1 - mean)*rstd*lnw[lane+32] + lnb[lane+32];
    }
    for (int i = tid; i < SS*64; i += 256) g_u[b*SS*64 + i] = 0.f;
    if (tid < SS) { g_den[b*SS + tid] = 0.f; g_c2[b*SS + tid] = 0.f; }
    __syncthreads();

    for (int i = tid; i < SS*64; i += 256) {
        int s = i >> 6, tc = i & 63;
        float acc = 0.f;
        #pragma unroll 8
        for (int e = 0; e < 64; e++)
            acc += sn[s*64 + e] * g_M[e*64 + tc];
        qtmp[i] = acc;
        g_qt[b*SS*64 + i] = acc * w_in[tc];
    }
    __syncthreads();
    if (tid < 14) {
        int s = tid >> 1;
        float acc = 0.f;
        if ((tid & 1) == 0) {
            for (int tc = 0; tc < 64; tc++) acc += qtmp[s*64+tc] * w_in[tc];
        } else {
            for (int tc = 0; tc < 64; tc++) acc += qtmp[s*64+tc] * b_in[tc];
        }
        g_qsc[b*SS*2 + tid] = acc;
    }
}

// ---------------------------------------------------------------------------
// Streaming pass. Raw x only; LN folded into qw/sw/sb + (den,c2) scalars.
// grid = (N/TILE, B), block = 128, dynamic smem.
// layout (floats): xs 8704 | qw 448 | qsc 16 | ps2 2048 | mtok 128 | psum 1792
#define A_SMEM_FLOATS 13136

__global__ void __launch_bounds__(128) k_attn(const float* __restrict__ inputs) {
    extern __shared__ float smf[];
    float4* xs   = (float4*)smf;                 // [128][17]
    float*  qw   = smf + 8704;                   // [7][64]
    float*  qsc  = qw + 448;                     // [7][2]
    float2* ps2  = (float2*)(qsc + 16);          // [128][8] {p, p*r}
    float*  mtok = qsc + 16 + 2048;              // [128]
    float4* psum = (float4*)(smf + 11344);       // [4][7][16]

    int b = blockIdx.y, tile = blockIdx.x;
    int tid = threadIdx.x;

    for (int i = tid; i < SS*64; i += 128) qw[i] = g_qt[b*SS*64 + i];
    if (tid < 14) qsc[tid] = g_qsc[b*SS*2 + tid];

    const float4* src4 = (const float4*)(inputs +
                         ((size_t)b*NN + (size_t)tile*TILE) * DD);
    #pragma unroll
    for (int k = 0; k < 16; k++) {
        int j = tid + 128*k;
        xs[(j >> 4)*PADF4 + (j & 15)] = src4[j];
    }
    __syncthreads();

    // phase A: per-token stats + 7 dots vs qw -> softmax
    {
        const float4* row = xs + tid*PADF4;
        const float4* qw4 = (const float4*)qw;
        float dot[SS];
        #pragma unroll
        for (int s = 0; s < SS; s++) dot[s] = 0.f;
        float sum = 0.f, sq = 0.f;
        #pragma unroll
        for (int k = 0; k < 16; k++) {
            float4 v = row[k];
            sum += v.x + v.y + v.z + v.w;
            sq  += v.x*v.x + v.y*v.y + v.z*v.z + v.w*v.w;
            #pragma unroll
            for (int s = 0; s < SS; s++) {
                float4 qv = qw4[s*16 + k];
                dot[s] += v.x*qv.x + v.y*qv.y + v.z*qv.z + v.w*qv.w;
            }
        }
        float m = sum * (1.f/64.f);
        float var = sq * (1.f/64.f) - m*m;
        float r = rsqrtf(var + LN_EPS);

        float lg[SS];
        #pragma unroll
        for (int s = 0; s < SS; s++)
            lg[s] = r*(dot[s] - m*qsc[2*s]) + qsc[2*s+1];
        float mx = lg[0];
        #pragma unroll
        for (int s = 1; s < SS; s++) mx = fmaxf(mx, lg[s]);
        float ex[SS], tot = 0.f;
        #pragma unroll
        for (int s = 0; s < SS; s++) { ex[s] = expf(lg[s] - mx); tot += ex[s]; }
        float inv = 1.f / tot;
        #pragma unroll
        for (int s = 0; s < SS; s++) {
            float p = ex[s]*inv + EPSV;
            ps2[tid*8 + s] = make_float2(p, p*r);
        }
        mtok[tid] = m;
    }
    __syncthreads();

    // phase B: G1 partials; each x element read exactly once.
    // Lanes 0..15 (h=0) and 16..31 (h=1) split tokens; butterfly-combine
    // the h-pair before lane<16 writes the warp partial.
    {
        int w = tid >> 5, lane = tid & 31;
        int h = lane >> 4, e4 = lane & 15;
        float4 acc[SS];
        #pragma unroll
        for (int s = 0; s < SS; s++) acc[s] = make_float4(0.f,0.f,0.f,0.f);
        #pragma unroll 4
        for (int j = 0; j < 16; j++) {
            int t = w*32 + (j << 1) + h;
            float4 xv = xs[t*PADF4 + e4];
            #pragma unroll
            for (int s = 0; s < SS; s++) {
                float pr = ps2[t*8 + s].y;
                acc[s].x += pr*xv.x; acc[s].y += pr*xv.y;
                acc[s].z += pr*xv.z; acc[s].w += pr*xv.w;
            }
        }
        #pragma unroll
        for (int s = 0; s < SS; s++) {
            acc[s].x += __shfl_xor_sync(0xffffffffu, acc[s].x, 16);
            acc[s].y += __shfl_xor_sync(0xffffffffu, acc[s].y, 16);
            acc[s].z += __shfl_xor_sync(0xffffffffu, acc[s].z, 16);
            acc[s].w += __shfl_xor_sync(0xffffffffu, acc[s].w, 16);
            if (h == 0)
                psum[(w*SS + s)*16 + e4] = acc[s];
        }
    }
    __syncthreads();

    if (tid < 112) {
        int s = tid >> 4, e4 = tid & 15;
        float4 a = psum[s*16+e4], b1 = psum[(SS+s)*16+e4],
               c = psum[(2*SS+s)*16+e4], d = psum[(3*SS+s)*16+e4];
        float4 t4 = make_float4(a.x+b1.x+c.x+d.x, a.y+b1.y+c.y+d.y,
                                a.z+b1.z+c.z+d.z, a.w+b1.w+c.w+d.w);
        float* up = g_u + (b*SS + s)*DD + e4*4;
        atomicAdd(up+0, t4.x); atomicAdd(up+1, t4.y);
        atomicAdd(up+2, t4.z); atomicAdd(up+3, t4.w);
    } else if (tid < 119) {
        int s = tid - 112;
        float d = 0.f;
        for (int t = 0; t < TILE; t++) d += ps2[t*8 + s].x;
        atomicAdd(&g_den[b*SS + s], d);
    } else if (tid < 126) {
        int s = tid - 119;
        float c = 0.f;
        for (int t = 0; t < TILE; t++) c += ps2[t*8 + s].y * mtok[t];
        atomicAdd(&g_c2[b*SS + s], c);
    }
}

// ---------------------------------------------------------------------------
// finalize: 4 batches per block. Weights staged once (odd-pitch smem).
#define BPB 4
#define F_OFF_C    0
#define F_OFF_WHH  (F_OFF_C   + 192*65)
#define F_OFF_W1   (F_OFF_WHH + 192*65)
#define F_OFF_W2   (F_OFF_W1  + 128*65)
#define F_OFF_M    (F_OFF_W2  + 64*129)
#define F_OFF_A    (F_OFF_M   + 64*65)
// per-batch scratch within F_OFF_A:
#define A_UP   0
#define A_PREV 448
#define A_GI   896
#define A_GH   2240
#define A_ACT  3584
#define A_MLN  4032
#define A_H1   4480
#define A_SN   5376
#define F_SMEM_FLOATS (F_OFF_A + 5824)

__global__ void __launch_bounds__(256) k_finalize(
        const float* __restrict__ W_hh,
        const float* __restrict__ b_ih,
        const float* __restrict__ b_hh,
        const float* __restrict__ W1,
        const float* __restrict__ b1,
        const float* __restrict__ W2,
        const float* __restrict__ b2,
        const float* __restrict__ ln_mlp_w,
        const float* __restrict__ ln_mlp_b,
        const float* __restrict__ ln_slots_w,
        const float* __restrict__ ln_slots_b,
        const float* __restrict__ ln_in_w,
        const float* __restrict__ ln_in_b,
        float* __restrict__ out, int last) {
    extern __shared__ float sm[];
    int tid = threadIdx.x;
    int w = tid >> 5, lane = tid & 31;

    for (int i = tid; i < 192*64; i += 256) sm[F_OFF_C   + i + (i>>6)] = g_C[i];
    for (int i = tid; i < 192*64; i += 256) sm[F_OFF_WHH + i + (i>>6)] = W_hh[i];
    for (int i = tid; i < 128*64; i += 256) sm[F_OFF_W1  + i + (i>>6)] = W1[i];
    for (int i = tid; i < 64*128; i += 256) sm[F_OFF_W2  + i + (i>>7)] = W2[i];
    for (int i = tid; i < 64*64;  i += 256) sm[F_OFF_M   + i + (i>>6)] = g_M[i];
    float* A = sm + F_OFF_A;
    __syncthreads();

    for (int bl = 0; bl < BPB; bl++) {
        int b = blockIdx.x * BPB + bl;

        // activations: upd = w_e*(G1-c2)/den + b_e ; prev slots
        for (int i = tid; i < SS*64; i += 256) {
            int s = i >> 6, e = i & 63;
            float invden = 1.f / g_den[b*SS + s];
            A[A_UP + i]   = ln_in_w[e] * (g_u[b*SS*64 + i] - g_c2[b*SS + s]) * invden
                            + ln_in_b[e];
            A[A_PREV + i] = g_slots[b*SS*64 + i];
        }
        __syncthreads();

        // gi = upd @ C^T + b_ih ; gh = prev @ W_hh^T + b_hh
        for (int i = tid; i < SS*192; i += 256) {
            int s = i / 192, j = i - s*192;
            float ai = b_ih[j], ah = b_hh[j];
            const float* cu = sm + F_OFF_C   + j*65;
            const float* ch = sm + F_OFF_WHH + j*65;
            const float* uu = A + A_UP   + s*64;
            const float* pp = A + A_PREV + s*64;
            #pragma unroll 8
            for (int e = 0; e < 64; e++) {
                ai += uu[e] * cu[e];
                ah += pp[e] * ch[e];
            }
            A[A_GI + i] = ai;
            A[A_GH + i] = ah;
        }
        __syncthreads();

        // GRU
        for (int i = tid; i < SS*64; i += 256) {
            int s = i >> 6, d = i & 63;
            float gir = A[A_GI + s*192 + d];
            float giz = A[A_GI + s*192 + 64 + d];
            float gin = A[A_GI + s*192 + 128 + d];
            float ghr = A[A_GH + s*192 + d];
            float ghz = A[A_GH + s*192 + 64 + d];
            float ghn = A[A_GH + s*192 + 128 + d];
            float r = 1.f / (1.f + expf(-(gir + ghr)));
            float z = 1.f / (1.f + expf(-(giz + ghz)));
            float n = tanhf(gin + r*ghn);
            A[A_ACT + i] = (1.f - z)*n + z*A[A_PREV + i];
        }
        __syncthreads();

        // LN (mlp)
        if (w < SS) {
            float v0 = A[A_ACT + w*64 + lane], v1 = A[A_ACT + w*64 + lane+32];
            float sum = v0 + v1, sq = v0*v0 + v1*v1;
            #pragma unroll
            for (int o = 16; o; o >>= 1) {
                sum += __shfl_xor_sync(0xffffffffu, sum, o);
                sq  += __shfl_xor_sync(0xffffffffu, sq,  o);
            }
            float mean = sum * (1.f/64.f);
            float var  = sq  * (1.f/64.f) - mean*mean;
            float rstd = rsqrtf(var + LN_EPS);
            A[A_MLN + w*64 + lane]    = (v0 - mean)*rstd*ln_mlp_w[lane]    + ln_mlp_b[lane];
            A[A_MLN + w*64 + lane+32] = (v1 - mean)*rstd*ln_mlp_w[lane+32] + ln_mlp_b[lane+32];
        }
        __syncthreads();

        // h1 = relu(mln @ W1^T + b1)
        for (int i = tid; i < SS*128; i += 256) {
            int s = i >> 7, j = i & 127;
            float acc = b1[j];
            const float* cw = sm + F_OFF_W1 + j*65;
            const float* mm = A + A_MLN + s*64;
            #pragma unroll 8
            for (int e = 0; e < 64; e++) acc += mm[e] * cw[e];
            A[A_H1 + i] = fmaxf(acc, 0.f);
        }
        __syncthreads();

        // res = newslot + h1 @ W2^T + b2
        for (int i = tid; i < SS*64; i += 256) {
            int s = i >> 6, d = i & 63;
            float acc = b2[d];
            const float* cw = sm + F_OFF_W2 + d*129;
            const float* hh = A + A_H1 + s*128;
            #pragma unroll 8
            for (int j = 0; j < 128; j++) acc += hh[j] * cw[j];
            float res = A[A_ACT + i] + acc;
            A[A_ACT + i] = res;
            g_slots[b*SS*64 + i] = res;
            if (last) out[b*SS*64 + i] = res;
        }
        __syncthreads();

        if (!last) {
            // next-iteration prep: LN(res)@M -> qw/sw/sb ; zero accumulators
            if (w < SS) {
                float v0 = A[A_ACT + w*64 + lane], v1 = A[A_ACT + w*64 + lane+32];
                float sum = v0 + v1, sq = v0*v0 + v1*v1;
                #pragma unroll
                for (int o = 16; o; o >>= 1) {
                    sum += __shfl_xor_sync(0xffffffffu, sum, o);
                    sq  += __shfl_xor_sync(0xffffffffu, sq,  o);
                }
                float mean = sum * (1.f/64.f);
                float var  = sq  * (1.f/64.f) - mean*mean;
                float rstd = rsqrtf(var + LN_EPS);
                A[A_SN + w*64 + lane]    = (v0 - mean)*rstd*ln_slots_w[lane]    + ln_slots_b[lane];
                A[A_SN + w*64 + lane+32] = (v1 - mean)*rstd*ln_slots_w[lane+32] + ln_slots_b[lane+32];
            }
            for (int i = tid; i < SS*64; i += 256) g_u[b*SS*64 + i] = 0.f;
            if (tid < SS) { g_den[b*SS + tid] = 0.f; g_c2[b*SS + tid] = 0.f; }
            __syncthreads();

            // qt into GI scratch, qw to global
            for (int i = tid; i < SS*64; i += 256) {
                int s = i >> 6, tc = i & 63;
                float acc = 0.f;
                const float* ss = A + A_SN + s*64;
                const float* mc = sm + F_OFF_M;
                #pragma unroll 8
                for (int e = 0; e < 64; e++) acc += ss[e] * mc[e*65 + tc];
                A[A_GI + i] = acc;
                g_qt[b*SS*64 + i] = acc * ln_in_w[tc];
            }
            __syncthreads();
            if (tid < 14) {
                int s = tid >> 1;
                float acc = 0.f;
                if ((tid & 1) == 0) {
                    for (int tc = 0; tc < 64; tc++) acc += A[A_GI + s*64+tc] * ln_in_w[tc];
                } else {
                    for (int tc = 0; tc < 64; tc++) acc += A[A_GI + s*64+tc] * ln_in_b[tc];
                }
                g_qsc[b*SS*2 + tid] = acc;
            }
        }
        __syncthreads();
    }
}

// ---------------------------------------------------------------------------
extern "C" void kernel_launch(void* const* d_in, const int* in_sizes, int n_in,
                              void* d_out, int out_size) {
    const float* inputs     = (const float*)d_in[0];
    const float* noise      = (const float*)d_in[1];
    const float* ln_in_w    = (const float*)d_in[2];
    const float* ln_in_b    = (const float*)d_in[3];
    const float* ln_slots_w = (const float*)d_in[4];
    const float* ln_slots_b = (const float*)d_in[5];
    const float* ln_mlp_w   = (const float*)d_in[6];
    const float* ln_mlp_b   = (const float*)d_in[7];
    const float* mu         = (const float*)d_in[8];
    const float* logsig     = (const float*)d_in[9];
    const float* Wq         = (const float*)d_in[10];
    const float* Wk         = (const float*)d_in[11];
    const float* Wv         = (const float*)d_in[12];
    const float* W_ih       = (const float*)d_in[13];
    const float* W_hh       = (const float*)d_in[14];
    const float* b_ih       = (const float*)d_in[15];
    const float* b_hh       = (const float*)d_in[16];
    const float* W1         = (const float*)d_in[17];
    const float* b1         = (const float*)d_in[18];
    const float* W2         = (const float*)d_in[19];
    const float* b2         = (const float*)d_in[20];
    float* out = (float*)d_out;

    cudaFuncSetAttribute(k_attn, cudaFuncAttributeMaxDynamicSharedMemorySize,
                         A_SMEM_FLOATS*4);
    cudaFuncSetAttribute(k_finalize, cudaFuncAttributeMaxDynamicSharedMemorySize,
                         F_SMEM_FLOATS*4);

    k_init_slots<<<(BB*SS*DD + 255)/256, 256>>>(noise, mu, logsig);
    k_precomp<<<64, 256>>>(Wq, Wk, W_ih, Wv);
    k_q0<<<BB, 256>>>(ln_slots_w, ln_slots_b, ln_in_w, ln_in_b);
    for (int it = 0; it < NUM_ITERS; it++) {
        dim3 grid(NN/TILE, BB);
        k_attn<<<grid, 128, A_SMEM_FLOATS*4>>>(inputs);
        k_finalize<<<BB/BPB, 256, F_SMEM_FLOATS*4>>>(
            W_hh, b_ih, b_hh, W1, b1, W2, b2,
            ln_mlp_w, ln_mlp_b, ln_slots_w, ln_slots_b,
            ln_in_w, ln_in_b,
            out, it == NUM_ITERS - 1 ? 1 : 0);
    }
}

// round 5
// speedup vs baseline: 1.1849x; 1.1849x over previous
#include <cuda_runtime.h>
#include <math.h>

#define BB 128
#define NN 4096
#define DD 64
#define SS 7
#define HH 128
#define NUM_ITERS 3
#define EPSV 1e-8f
#define LN_EPS 1e-5f
#define SCALE 0.125f   // 64^-0.5

#define TILE 128
#define HALF 64

// persistent scratch (no allocation allowed)
__device__ float g_slots[BB*SS*DD];
__device__ float g_qt[BB*SS*DD];    // qw = (ln_in_w ⊙ qt)   [b][s][64]
__device__ float g_qsc[BB*SS*2];    // {sw, sb} per (b,s)
__device__ float g_u[BB*SS*DD];     // G1 = sum_n (p*r) * x
__device__ float g_den[BB*SS];      // sum_n p
__device__ float g_c2[BB*SS];       // sum_n p*r*m
__device__ float g_M[DD*DD];        // scale * Wq^T @ Wk      [e][t]
__device__ float g_CT[DD*3*DD];     // (W_ih @ Wv)^T          [e][j]  64x192
__device__ float g_WHHT[DD*3*DD];   // W_hh^T                 [e][j]  64x192
__device__ float g_W1T[DD*HH];      // W1^T                   [e][j]  64x128
__device__ float g_W2T[HH*DD];      // W2^T                   [j][d]  128x64

// ---------------------------------------------------------------------------
__global__ void k_init_slots(const float* __restrict__ noise,
                             const float* __restrict__ mu,
                             const float* __restrict__ logsig) {
    int i = blockIdx.x * blockDim.x + threadIdx.x;
    if (i < BB*SS*DD) {
        int d = i & 63;
        g_slots[i] = mu[d] + expf(logsig[d]) * noise[i];
    }
}

// ---------------------------------------------------------------------------
// blocks 0..15: M ; 16..63: CT (dot) ; 64..175: transposes WHHT/W1T/W2T
__global__ void k_precomp(const float* __restrict__ Wq,
                          const float* __restrict__ Wk,
                          const float* __restrict__ W_ih,
                          const float* __restrict__ Wv,
                          const float* __restrict__ W_hh,
                          const float* __restrict__ W1,
                          const float* __restrict__ W2) {
    int bi = blockIdx.x, t = threadIdx.x;
    if (bi < 16) {
        int o = bi*256 + t;
        int e = o >> 6, tc = o & 63;
        float acc = 0.f;
        #pragma unroll 8
        for (int d = 0; d < 64; d++)
            acc += Wq[d*64 + e] * Wk[d*64 + tc];
        g_M[e*64 + tc] = acc * SCALE;
    } else if (bi < 64) {
        int o = (bi-16)*256 + t;        // o = e*192 + j
        int e = o / 192, j = o - e*192;
        float acc = 0.f;
        #pragma unroll 8
        for (int h = 0; h < 64; h++)
            acc += W_ih[j*64 + h] * Wv[h*64 + e];
        g_CT[o] = acc;
    } else {
        int idx = (bi-64)*256 + t;
        if (idx < 12288) {
            int e = idx / 192, j = idx - e*192;
            g_WHHT[idx] = W_hh[j*64 + e];
        } else if (idx < 20480) {
            int o = idx - 12288;
            int e = o >> 7, j = o & 127;
            g_W1T[o] = W1[j*64 + e];
        } else {
            int o = idx - 20480;
            int j = o >> 6, d = o & 63;
            g_W2T[o] = W2[d*128 + j];
        }
    }
}

// ---------------------------------------------------------------------------
// Initial q prep: qt = LN(slots)@M ; qw = qt*w_in ; sw,sb ; zero accumulators.
__global__ void k_q0(const float* __restrict__ lnw,
                     const float* __restrict__ lnb,
                     const float* __restrict__ w_in,
                     const float* __restrict__ b_in) {
    int b = blockIdx.x;
    int tid = threadIdx.x;
    int w = tid >> 5, lane = tid & 31;
    __shared__ float sn[SS*64];
    __shared__ float qtmp[SS*64];

    if (w < SS) {
        const float* sl = g_slots + (b*SS + w)*DD;
        float v0 = sl[lane], v1 = sl[lane+32];
        float sum = v0 + v1, sq = v0*v0 + v1*v1;
        #pragma unroll
        for (int o = 16; o; o >>= 1) {
            sum += __shfl_xor_sync(0xffffffffu, sum, o);
            sq  += __shfl_xor_sync(0xffffffffu, sq,  o);
        }
        float mean = sum * (1.f/64.f);
        float var  = sq  * (1.f/64.f) - mean*mean;
        float rstd = rsqrtf(var + LN_EPS);
        sn[w*64 + lane]    = (v0 - mean)*rstd*lnw[lane]    + lnb[lane];
        sn[w*64 + lane+32] = (v1 - mean)*rstd*lnw[lane+32] + lnb[lane+32];
    }
    for (int i = tid; i < SS*64; i += 256) g_u[b*SS*64 + i] = 0.f;
    if (tid < SS) { g_den[b*SS + tid] = 0.f; g_c2[b*SS + tid] = 0.f; }
    __syncthreads();

    for (int i = tid; i < SS*64; i += 256) {
        int s = i >> 6, tc = i & 63;
        float acc = 0.f;
        #pragma unroll 8
        for (int e = 0; e < 64; e++)
            acc += sn[s*64 + e] * g_M[e*64 + tc];
        qtmp[i] = acc;
        g_qt[b*SS*64 + i] = acc * w_in[tc];
    }
    __syncthreads();
    if (tid < 14) {
        int s = tid >> 1;
        float acc = 0.f;
        if ((tid & 1) == 0) {
            for (int tc = 0; tc < 64; tc++) acc += qtmp[s*64+tc] * w_in[tc];
        } else {
            for (int tc = 0; tc < 64; tc++) acc += qtmp[s*64+tc] * b_in[tc];
        }
        g_qsc[b*SS*2 + tid] = acc;
    }
}

// ---------------------------------------------------------------------------
// Streaming pass: tile of 128 tokens processed as two 64-token halves.
// smem (floats): xs 4352 | qw 448 | qsc 16 | part 640 | ps 512 | psum 1792
#define A_XS   0
#define A_QW   4352
#define A_QSC  4800
#define A_PART 4816
#define A_PS   5456
#define A_PSUM 5968
#define A_SMEM_FLOATS 7760

__global__ void __launch_bounds__(128) k_attn(const float* __restrict__ inputs) {
    extern __shared__ float smf[];
    float4* xs   = (float4*)(smf + A_XS);      // [64][17] float4
    float*  qw   = smf + A_QW;                 // [7][64]
    float*  qsc  = smf + A_QSC;                // [7][2]
    float*  part = smf + A_PART;               // [64][10]
    float*  ps   = smf + A_PS;                 // [64][8]  (p*r)
    float4* psum = (float4*)(smf + A_PSUM);    // [4][7][16]

    int b = blockIdx.y, tile = blockIdx.x;
    int tid = threadIdx.x;
    int w = tid >> 5, lane = tid & 31;
    int h = lane >> 4, e4 = lane & 15;

    for (int i = tid; i < SS*64; i += 128) qw[i] = g_qt[b*SS*64 + i];
    if (tid < 14) qsc[tid] = g_qsc[b*SS*2 + tid];

    float4 acc[SS];
    #pragma unroll
    for (int s = 0; s < SS; s++) acc[s] = make_float4(0.f,0.f,0.f,0.f);

    const float4* src4 = (const float4*)(inputs +
                         ((size_t)b*NN + (size_t)tile*TILE) * DD);

    for (int half = 0; half < 2; half++) {
        // stage 64 tokens (coalesced)
        #pragma unroll
        for (int k = 0; k < 8; k++) {
            int j = tid + 128*k;
            xs[(j >> 4)*17 + (j & 15)] = src4[half*1024 + j];
        }
        __syncthreads();

        // phase A partials: token = tid&63, k-range split by tid>>6
        int t = tid & 63;
        int k0 = (tid >> 6) * 8;
        float dot[SS];
        #pragma unroll
        for (int s = 0; s < SS; s++) dot[s] = 0.f;
        float sum = 0.f, sq = 0.f;
        {
            const float4* row = xs + t*17 + k0;
            const float4* qw4 = (const float4*)qw;
            #pragma unroll
            for (int k = 0; k < 8; k++) {
                float4 v = row[k];
                sum += v.x + v.y + v.z + v.w;
                sq  += v.x*v.x + v.y*v.y + v.z*v.z + v.w*v.w;
                #pragma unroll
                for (int s = 0; s < SS; s++) {
                    float4 qv = qw4[s*16 + k0 + k];
                    dot[s] += v.x*qv.x + v.y*qv.y + v.z*qv.z + v.w*qv.w;
                }
            }
        }
        if (tid >= 64) {
            part[t*10 + 0] = sum;
            part[t*10 + 1] = sq;
            #pragma unroll
            for (int s = 0; s < SS; s++) part[t*10 + 2 + s] = dot[s];
        }
        __syncthreads();

        if (tid < 64) {
            sum += part[t*10 + 0];
            sq  += part[t*10 + 1];
            #pragma unroll
            for (int s = 0; s < SS; s++) dot[s] += part[t*10 + 2 + s];

            float m = sum * (1.f/64.f);
            float var = sq * (1.f/64.f) - m*m;
            float r = rsqrtf(var + LN_EPS);

            float lg[SS];
            #pragma unroll
            for (int s = 0; s < SS; s++)
                lg[s] = r*(dot[s] - m*qsc[2*s]) + qsc[2*s+1];
            float mx = lg[0];
            #pragma unroll
            for (int s = 1; s < SS; s++) mx = fmaxf(mx, lg[s]);
            float ex[SS], tot = 0.f;
            #pragma unroll
            for (int s = 0; s < SS; s++) { ex[s] = expf(lg[s] - mx); tot += ex[s]; }
            float inv = 1.f / tot;
            #pragma unroll
            for (int s = 0; s < SS; s++) {
                float pv = ex[s]*inv + EPSV;
                float pr = pv*r;
                ps[t*8 + s] = pr;
                float dv = pv, cv = pr*m;
                #pragma unroll
                for (int o = 16; o; o >>= 1) {
                    dv += __shfl_xor_sync(0xffffffffu, dv, o);
                    cv += __shfl_xor_sync(0xffffffffu, cv, o);
                }
                if (lane == 0) {
                    atomicAdd(&g_den[b*SS + s], dv);
                    atomicAdd(&g_c2[b*SS + s],  cv);
                }
            }
        }
        __syncthreads();

        // phase B: accumulate G1; each xs element read once
        #pragma unroll
        for (int j = 0; j < 8; j++) {
            int tt = w*16 + (j << 1) + h;
            float4 xv = xs[tt*17 + e4];
            #pragma unroll
            for (int s = 0; s < SS; s++) {
                float pr = ps[tt*8 + s];
                acc[s].x += pr*xv.x; acc[s].y += pr*xv.y;
                acc[s].z += pr*xv.z; acc[s].w += pr*xv.w;
            }
        }
        __syncthreads();   // xs/ps reused next half
    }

    // combine h-pairs, then cross-warp via psum
    #pragma unroll
    for (int s = 0; s < SS; s++) {
        acc[s].x += __shfl_xor_sync(0xffffffffu, acc[s].x, 16);
        acc[s].y += __shfl_xor_sync(0xffffffffu, acc[s].y, 16);
        acc[s].z += __shfl_xor_sync(0xffffffffu, acc[s].z, 16);
        acc[s].w += __shfl_xor_sync(0xffffffffu, acc[s].w, 16);
        if (h == 0)
            psum[(w*SS + s)*16 + e4] = acc[s];
    }
    __syncthreads();

    if (tid < 112) {
        int s = tid >> 4, ee = tid & 15;
        float4 a = psum[s*16+ee], b1 = psum[(SS+s)*16+ee],
               c = psum[(2*SS+s)*16+ee], d = psum[(3*SS+s)*16+ee];
        float4 t4 = make_float4(a.x+b1.x+c.x+d.x, a.y+b1.y+c.y+d.y,
                                a.z+b1.z+c.z+d.z, a.w+b1.w+c.w+d.w);
        float* up = g_u + (b*SS + s)*DD + ee*4;
        atomicAdd(up+0, t4.x); atomicAdd(up+1, t4.y);
        atomicAdd(up+2, t4.z); atomicAdd(up+3, t4.w);
    }
}

// ---------------------------------------------------------------------------
// finalize: 1 batch per block, NO weight staging — coalesced global weights.
// smem = activations only (~23KB).
#define A_UP   0
#define A_PREV 448
#define A_GI   896
#define A_GH   2240
#define A_ACT  3584
#define A_MLN  4032
#define A_H1   4480
#define A_SN   5376

__global__ void __launch_bounds__(256) k_finalize(
        const float* __restrict__ b_ih,
        const float* __restrict__ b_hh,
        const float* __restrict__ b1,
        const float* __restrict__ b2,
        const float* __restrict__ ln_mlp_w,
        const float* __restrict__ ln_mlp_b,
        const float* __restrict__ ln_slots_w,
        const float* __restrict__ ln_slots_b,
        const float* __restrict__ ln_in_w,
        const float* __restrict__ ln_in_b,
        float* __restrict__ out, int last) {
    __shared__ float A[5824];
    int b = blockIdx.x;
    int tid = threadIdx.x;
    int w = tid >> 5, lane = tid & 31;

    // upd = w_e*(G1-c2)/den + b_e ; prev slots
    for (int i = tid; i < SS*64; i += 256) {
        int s = i >> 6, e = i & 63;
        float invden = 1.f / g_den[b*SS + s];
        A[A_UP + i]   = ln_in_w[e] * (g_u[b*SS*64 + i] - g_c2[b*SS + s]) * invden
                        + ln_in_b[e];
        A[A_PREV + i] = g_slots[b*SS*64 + i];
    }
    __syncthreads();

    // gi = upd @ C^T + b_ih ; gh = prev @ W_hh^T + b_hh  (coalesced weights)
    for (int i = tid; i < SS*192; i += 256) {
        int s = i / 192, j = i - s*192;
        float ai = b_ih[j], ah = b_hh[j];
        const float* uu = A + A_UP   + s*64;
        const float* pp = A + A_PREV + s*64;
        #pragma unroll 8
        for (int e = 0; e < 64; e++) {
            ai += uu[e] * g_CT[e*192 + j];
            ah += pp[e] * g_WHHT[e*192 + j];
        }
        A[A_GI + i] = ai;
        A[A_GH + i] = ah;
    }
    __syncthreads();

    // GRU
    for (int i = tid; i < SS*64; i += 256) {
        int s = i >> 6, d = i & 63;
        float r = 1.f / (1.f + expf(-(A[A_GI + s*192 + d]      + A[A_GH + s*192 + d])));
        float z = 1.f / (1.f + expf(-(A[A_GI + s*192 + 64 + d] + A[A_GH + s*192 + 64 + d])));
        float n = tanhf(A[A_GI + s*192 + 128 + d] + r*A[A_GH + s*192 + 128 + d]);
        A[A_ACT + i] = (1.f - z)*n + z*A[A_PREV + i];
    }
    __syncthreads();

    // LN (mlp)
    if (w < SS) {
        float v0 = A[A_ACT + w*64 + lane], v1 = A[A_ACT + w*64 + lane+32];
        float sum = v0 + v1, sq = v0*v0 + v1*v1;
        #pragma unroll
        for (int o = 16; o; o >>= 1) {
            sum += __shfl_xor_sync(0xffffffffu, sum, o);
            sq  += __shfl_xor_sync(0xffffffffu, sq,  o);
        }
        float mean = sum * (1.f/64.f);
        float var  = sq  * (1.f/64.f) - mean*mean;
        float rstd = rsqrtf(var + LN_EPS);
        A[A_MLN + w*64 + lane]    = (v0 - mean)*rstd*ln_mlp_w[lane]    + ln_mlp_b[lane];
        A[A_MLN + w*64 + lane+32] = (v1 - mean)*rstd*ln_mlp_w[lane+32] + ln_mlp_b[lane+32];
    }
    __syncthreads();

    // h1 = relu(mln @ W1^T + b1)
    for (int i = tid; i < SS*128; i += 256) {
        int s = i >> 7, j = i & 127;
        float acc = b1[j];
        const float* mm = A + A_MLN + s*64;
        #pragma unroll 8
        for (int e = 0; e < 64; e++) acc += mm[e] * g_W1T[e*128 + j];
        A[A_H1 + i] = fmaxf(acc, 0.f);
    }
    __syncthreads();

    // res = newslot + h1 @ W2^T + b2
    for (int i = tid; i < SS*64; i += 256) {
        int s = i >> 6, d = i & 63;
        float acc = b2[d];
        const float* hh = A + A_H1 + s*128;
        #pragma unroll 8
        for (int j = 0; j < 128; j++) acc += hh[j] * g_W2T[j*64 + d];
        float res = A[A_ACT + i] + acc;
        A[A_ACT + i] = res;
        g_slots[b*SS*64 + i] = res;
        if (last) out[b*SS*64 + i] = res;
    }
    __syncthreads();

    if (!last) {
        // next-iteration prep: LN(res)@M -> qw/sw/sb ; zero accumulators
        if (w < SS) {
            float v0 = A[A_ACT + w*64 + lane], v1 = A[A_ACT + w*64 + lane+32];
            float sum = v0 + v1, sq = v0*v0 + v1*v1;
            #pragma unroll
            for (int o = 16; o; o >>= 1) {
                sum += __shfl_xor_sync(0xffffffffu, sum, o);
                sq  += __shfl_xor_sync(0xffffffffu, sq,  o);
            }
            float mean = sum * (1.f/64.f);
            float var  = sq  * (1.f/64.f) - mean*mean;
            float rstd = rsqrtf(var + LN_EPS);
            A[A_SN + w*64 + lane]    = (v0 - mean)*rstd*ln_slots_w[lane]    + ln_slots_b[lane];
            A[A_SN + w*64 + lane+32] = (v1 - mean)*rstd*ln_slots_w[lane+32] + ln_slots_b[lane+32];
        }
        for (int i = tid; i < SS*64; i += 256) g_u[b*SS*64 + i] = 0.f;
        if (tid < SS) { g_den[b*SS + tid] = 0.f; g_c2[b*SS + tid] = 0.f; }
        __syncthreads();

        for (int i = tid; i < SS*64; i += 256) {
            int s = i >> 6, tc = i & 63;
            float acc = 0.f;
            const float* ss = A + A_SN + s*64;
            #pragma unroll 8
            for (int e = 0; e < 64; e++) acc += ss[e] * g_M[e*64 + tc];
            A[A_GI + i] = acc;
            g_qt[b*SS*64 + i] = acc * ln_in_w[tc];
        }
        __syncthreads();
        if (tid < 14) {
            int s = tid >> 1;
            float acc = 0.f;
            if ((tid & 1) == 0) {
                for (int tc = 0; tc < 64; tc++) acc += A[A_GI + s*64+tc] * ln_in_w[tc];
            } else {
                for (int tc = 0; tc < 64; tc++) acc += A[A_GI + s*64+tc] * ln_in_b[tc];
            }
            g_qsc[b*SS*2 + tid] = acc;
        }
    }
}

// ---------------------------------------------------------------------------
extern "C" void kernel_launch(void* const* d_in, const int* in_sizes, int n_in,
                              void* d_out, int out_size) {
    const float* inputs     = (const float*)d_in[0];
    const float* noise      = (const float*)d_in[1];
    const float* ln_in_w    = (const float*)d_in[2];
    const float* ln_in_b    = (const float*)d_in[3];
    const float* ln_slots_w = (const float*)d_in[4];
    const float* ln_slots_b = (const float*)d_in[5];
    const float* ln_mlp_w   = (const float*)d_in[6];
    const float* ln_mlp_b   = (const float*)d_in[7];
    const float* mu         = (const float*)d_in[8];
    const float* logsig     = (const float*)d_in[9];
    const float* Wq         = (const float*)d_in[10];
    const float* Wk         = (const float*)d_in[11];
    const float* Wv         = (const float*)d_in[12];
    const float* W_ih       = (const float*)d_in[13];
    const float* W_hh       = (const float*)d_in[14];
    const float* b_ih       = (const float*)d_in[15];
    const float* b_hh       = (const float*)d_in[16];
    const float* W1         = (const float*)d_in[17];
    const float* b1         = (const float*)d_in[18];
    const float* W2         = (const float*)d_in[19];
    const float* b2         = (const float*)d_in[20];
    float* out = (float*)d_out;

    cudaFuncSetAttribute(k_attn, cudaFuncAttributeMaxDynamicSharedMemorySize,
                         A_SMEM_FLOATS*4);

    k_init_slots<<<(BB*SS*DD + 255)/256, 256>>>(noise, mu, logsig);
    k_precomp<<<176, 256>>>(Wq, Wk, W_ih, Wv, W_hh, W1, W2);
    k_q0<<<BB, 256>>>(ln_slots_w, ln_slots_b, ln_in_w, ln_in_b);
    for (int it = 0; it < NUM_ITERS; it++) {
        dim3 grid(NN/TILE, BB);
        k_attn<<<grid, 128, A_SMEM_FLOATS*4>>>(inputs);
        k_finalize<<<BB, 256>>>(b_ih, b_hh, b1, b2,
                                ln_mlp_w, ln_mlp_b, ln_slots_w, ln_slots_b,
                                ln_in_w, ln_in_b,
                                out, it == NUM_ITERS - 1 ? 1 : 0);
    }
}

// round 6
// speedup vs baseline: 1.7454x; 1.4730x over previous
#include <cuda_runtime.h>
#include <math.h>

#define BB 128
#define NN 4096
#define DD 64
#define SS 7
#define HH 128
#define NUM_ITERS 3
#define EPSV 1e-8f
#define LN_EPS 1e-5f
#define SCALE 0.125f   // 64^-0.5

typedef unsigned long long u64;

// persistent scratch (no allocation allowed)
__device__ float g_slots[BB*SS*DD];
__device__ float g_qt[BB*SS*DD];    // qw = ln_in_w ⊙ (q@Wk)  [b][s][64]
__device__ float g_qsc[BB*SS*2];    // {sw, sb} per (b,s)
__device__ float g_u[BB*SS*DD];     // G1 = sum_n (p*r) * x
__device__ float g_den[BB*SS];      // sum_n p
__device__ float g_c2[BB*SS];       // sum_n p*r*m
__device__ float g_M[DD*DD];        // scale * Wq^T @ Wk      [e][t]
__device__ float g_CT[DD*3*DD];     // (W_ih @ Wv)^T          [e][j]
__device__ float g_WHHT[DD*3*DD];   // W_hh^T                 [e][j]
__device__ float g_W1T[DD*HH];      // W1^T                   [e][j]
__device__ float g_W2T[HH*DD];      // W2^T                   [j][d]

// ---------------------------------------------------------------------------
__device__ __forceinline__ u64 pk(float lo, float hi){
    u64 r; asm("mov.b64 %0,{%1,%2};" : "=l"(r) : "f"(lo), "f"(hi)); return r;
}
__device__ __forceinline__ void upk(u64 v, float& lo, float& hi){
    asm("mov.b64 {%0,%1},%2;" : "=f"(lo), "=f"(hi) : "l"(v));
}
__device__ __forceinline__ void fma2(u64& d, u64 a, u64 b){
    asm("fma.rn.f32x2 %0,%1,%2,%0;" : "+l"(d) : "l"(a), "l"(b));
}
__device__ __forceinline__ void add2(u64& d, u64 a){
    asm("add.rn.f32x2 %0,%1,%0;" : "+l"(d) : "l"(a));
}
// fast exp: exp2 split with magic bias + degree-6 poly (rel err ~1e-7)
__device__ __forceinline__ float fexp(float x){
    float t = fmaxf(x * 1.4426950408889634f, -126.f);
    float z = __fadd_rn(t, 12582912.f);
    int n = __float_as_int(z) - 0x4B400000;
    float f = t - __fsub_rn(z, 12582912.f);
    float p =         1.5403530e-4f;
    p = fmaf(p, f,    1.3333558e-3f);
    p = fmaf(p, f,    9.6181291e-3f);
    p = fmaf(p, f,    5.5504109e-2f);
    p = fmaf(p, f,    2.4022651e-1f);
    p = fmaf(p, f,    6.9314718e-1f);
    p = fmaf(p, f,    1.0f);
    return p * __int_as_float((n + 127) << 23);
}

// ---------------------------------------------------------------------------
__global__ void k_init_slots(const float* __restrict__ noise,
                             const float* __restrict__ mu,
                             const float* __restrict__ logsig) {
    int i = blockIdx.x * blockDim.x + threadIdx.x;
    if (i < BB*SS*DD) {
        int d = i & 63;
        g_slots[i] = mu[d] + expf(logsig[d]) * noise[i];
    }
}

// ---------------------------------------------------------------------------
// blocks 0..15: M ; 16..63: CT (dot) ; 64..175: transposes WHHT/W1T/W2T
__global__ void k_precomp(const float* __restrict__ Wq,
                          const float* __restrict__ Wk,
                          const float* __restrict__ W_ih,
                          const float* __restrict__ Wv,
                          const float* __restrict__ W_hh,
                          const float* __restrict__ W1,
                          const float* __restrict__ W2) {
    int bi = blockIdx.x, t = threadIdx.x;
    if (bi < 16) {
        int o = bi*256 + t;
        int e = o >> 6, tc = o & 63;
        float acc = 0.f;
        #pragma unroll 8
        for (int d = 0; d < 64; d++)
            acc += Wq[d*64 + e] * Wk[d*64 + tc];
        g_M[e*64 + tc] = acc * SCALE;
    } else if (bi < 64) {
        int o = (bi-16)*256 + t;        // o = e*192 + j
        int e = o / 192, j = o - e*192;
        float acc = 0.f;
        #pragma unroll 8
        for (int h = 0; h < 64; h++)
            acc += W_ih[j*64 + h] * Wv[h*64 + e];
        g_CT[o] = acc;
    } else {
        int idx = (bi-64)*256 + t;
        if (idx < 12288) {
            int e = idx / 192, j = idx - e*192;
            g_WHHT[idx] = W_hh[j*64 + e];
        } else if (idx < 20480) {
            int o = idx - 12288;
            int e = o >> 7, j = o & 127;
            g_W1T[o] = W1[j*64 + e];
        } else {
            int o = idx - 20480;
            int j = o >> 6, d = o & 63;
            g_W2T[o] = W2[d*128 + j];
        }
    }
}

// ---------------------------------------------------------------------------
// Initial q prep: qt = LN(slots)@M ; qw = qt*w_in ; sw,sb ; zero accumulators.
__global__ void k_q0(const float* __restrict__ lnw,
                     const float* __restrict__ lnb,
                     const float* __restrict__ w_in,
                     const float* __restrict__ b_in) {
    int b = blockIdx.x;
    int tid = threadIdx.x;
    int w = tid >> 5, lane = tid & 31;
    __shared__ float sn[SS*64];
    __shared__ float qtmp[SS*64];

    if (w < SS) {
        const float* sl = g_slots + (b*SS + w)*DD;
        float v0 = sl[lane], v1 = sl[lane+32];
        float sum = v0 + v1, sq = v0*v0 + v1*v1;
        #pragma unroll
        for (int o = 16; o; o >>= 1) {
            sum += __shfl_xor_sync(0xffffffffu, sum, o);
            sq  += __shfl_xor_sync(0xffffffffu, sq,  o);
        }
        float mean = sum * (1.f/64.f);
        float var  = sq  * (1.f/64.f) - mean*mean;
        float rstd = rsqrtf(var + LN_EPS);
        sn[w*64 + lane]    = (v0 - mean)*rstd*lnw[lane]    + lnb[lane];
        sn[w*64 + lane+32] = (v1 - mean)*rstd*lnw[lane+32] + lnb[lane+32];
    }
    for (int i = tid; i < SS*64; i += 256) g_u[b*SS*64 + i] = 0.f;
    if (tid < SS) { g_den[b*SS + tid] = 0.f; g_c2[b*SS + tid] = 0.f; }
    __syncthreads();

    for (int i = tid; i < SS*64; i += 256) {
        int s = i >> 6, tc = i & 63;
        float acc = 0.f;
        #pragma unroll 8
        for (int e = 0; e < 64; e++)
            acc += sn[s*64 + e] * g_M[e*64 + tc];
        qtmp[i] = acc;
        g_qt[b*SS*64 + i] = acc * w_in[tc];
    }
    __syncthreads();
    if (tid < 14) {
        int s = tid >> 1;
        float acc = 0.f;
        if ((tid & 1) == 0) {
            for (int tc = 0; tc < 64; tc++) acc += qtmp[s*64+tc] * w_in[tc];
        } else {
            for (int tc = 0; tc < 64; tc++) acc += qtmp[s*64+tc] * b_in[tc];
        }
        g_qsc[b*SS*2 + tid] = acc;
    }
}

// ---------------------------------------------------------------------------
// Streaming pass, warp-independent: each warp owns 32 tokens end-to-end.
// smem floats: xs 4*2176 | qw 448 | qsc 16 | psr 4*512
#define AT_XS   0
#define AT_QW   8704
#define AT_QSC  9152
#define AT_PSR  9168
#define AT_TOT  11216

__global__ void __launch_bounds__(128) k_attn(const float* __restrict__ inputs) {
    extern __shared__ float smf[];
    int b = blockIdx.y, tile = blockIdx.x;
    int tid = threadIdx.x;
    int w = tid >> 5, lane = tid & 31;

    for (int i = tid; i < SS*64; i += 128) smf[AT_QW + i] = g_qt[b*SS*64 + i];
    if (tid < 14) smf[AT_QSC + tid] = g_qsc[b*14 + tid];

    float4* xsw = (float4*)(smf + AT_XS + w*2176);
    const float4* src4 = (const float4*)(inputs +
                         ((size_t)b*NN + (size_t)tile*128 + w*32) * DD);
    #pragma unroll
    for (int k = 0; k < 16; k++) {
        int idx = lane + 32*k;
        xsw[(idx >> 4)*17 + (idx & 15)] = src4[idx];
    }
    __syncthreads();

    // phase A: token per thread (t = lane), packed f32x2 math
    {
        const float4* row = xsw + lane*17;
        const u64* qwu = (const u64*)(smf + AT_QW);
        u64 dot2[SS];
        #pragma unroll
        for (int s = 0; s < SS; s++) dot2[s] = 0;
        u64 sum2 = 0, sq2 = 0;
        #pragma unroll
        for (int k = 0; k < 16; k++) {
            float4 v = row[k];
            u64 a = pk(v.x, v.y), c = pk(v.z, v.w);
            add2(sum2, a); add2(sum2, c);
            fma2(sq2, a, a); fma2(sq2, c, c);
            #pragma unroll
            for (int s = 0; s < SS; s++) {
                fma2(dot2[s], a, qwu[s*32 + 2*k]);
                fma2(dot2[s], c, qwu[s*32 + 2*k + 1]);
            }
        }
        float lo, hi;
        upk(sum2, lo, hi); float sum = lo + hi;
        upk(sq2,  lo, hi); float sq  = lo + hi;
        float m = sum * (1.f/64.f);
        float vr = fmaf(sq, 1.f/64.f, -m*m) + LN_EPS;
        float r = rsqrtf(vr);
        float inv_r = vr * r;

        float lg[SS];
        #pragma unroll
        for (int s = 0; s < SS; s++) {
            upk(dot2[s], lo, hi);
            float d = lo + hi;
            float t1 = fmaf(-m, smf[AT_QSC + 2*s], d);
            lg[s] = fmaf(r, t1, smf[AT_QSC + 2*s + 1]);
        }
        float mx = lg[0];
        #pragma unroll
        for (int s = 1; s < SS; s++) mx = fmaxf(mx, lg[s]);
        float ex[SS], tot = 0.f;
        #pragma unroll
        for (int s = 0; s < SS; s++) { ex[s] = fexp(lg[s] - mx); tot += ex[s]; }
        float inv = __fdividef(1.f, tot);

        u64* psr = (u64*)(smf + AT_PSR) + w*256 + lane*8;
        #pragma unroll
        for (int s = 0; s < SS; s++) {
            float p  = fmaf(ex[s], inv, EPSV);
            float pr = p * r;
            psr[s] = pk(pr, pr);
        }
        psr[7] = pk(inv_r, m);
    }
    __syncwarp();

    // den / c2 (lanes 0..13): p = pr*inv_r, c2 term = pr*m
    if (lane < 14) {
        int s7 = (lane < 7) ? lane : lane - 7;
        int hf = (lane < 7) ? 0 : 1;
        const float* base = smf + AT_PSR + w*512;
        float val = 0.f;
        #pragma unroll
        for (int t = 0; t < 32; t++)
            val += base[(t*8 + s7)*2] * base[t*16 + 14 + hf];
        if (lane < 7) atomicAdd(&g_den[b*SS + s7], val);
        else          atomicAdd(&g_c2[b*SS + s7],  val);
    }

    // phase B: warp-local outer product, packed
    {
        int h = lane >> 4, e4 = lane & 15;
        const u64* psru = (const u64*)(smf + AT_PSR) + w*256;
        u64 acca[SS], accb[SS];
        #pragma unroll
        for (int s = 0; s < SS; s++) { acca[s] = 0; accb[s] = 0; }
        #pragma unroll
        for (int j = 0; j < 16; j++) {
            int t = 2*j + h;
            float4 xv = xsw[t*17 + e4];
            u64 xa = pk(xv.x, xv.y), xb = pk(xv.z, xv.w);
            #pragma unroll
            for (int s = 0; s < SS; s++) {
                u64 pr2 = psru[t*8 + s];
                fma2(acca[s], xa, pr2);
                fma2(accb[s], xb, pr2);
            }
        }
        float4* psumw = (float4*)(smf + AT_XS + w*2176);   // reuse own xs
        #pragma unroll
        for (int s = 0; s < SS; s++) {
            u64 oa = __shfl_xor_sync(0xffffffffu, acca[s], 16);
            u64 ob = __shfl_xor_sync(0xffffffffu, accb[s], 16);
            add2(acca[s], oa); add2(accb[s], ob);
            if (h == 0) {
                float4 o;
                upk(acca[s], o.x, o.y);
                upk(accb[s], o.z, o.w);
                psumw[s*16 + e4] = o;
            }
        }
    }
    __syncthreads();

    if (tid < 112) {
        int s = tid >> 4, e4 = tid & 15;
        float4 acc = make_float4(0.f, 0.f, 0.f, 0.f);
        #pragma unroll
        for (int w2 = 0; w2 < 4; w2++) {
            float4 v = ((const float4*)(smf + AT_XS + w2*2176))[s*16 + e4];
            acc.x += v.x; acc.y += v.y; acc.z += v.z; acc.w += v.w;
        }
        float* up = g_u + (b*SS + s)*DD + e4*4;
        atomicAdd(up+0, acc.x); atomicAdd(up+1, acc.y);
        atomicAdd(up+2, acc.z); atomicAdd(up+3, acc.w);
    }
}

// ---------------------------------------------------------------------------
// finalize: one block per (batch, slot) = 896 blocks, 192 threads.
__global__ void __launch_bounds__(192) k_finalize(
        const float* __restrict__ b_ih, const float* __restrict__ b_hh,
        const float* __restrict__ b1,  const float* __restrict__ b2,
        const float* __restrict__ ln_mlp_w, const float* __restrict__ ln_mlp_b,
        const float* __restrict__ ln_slots_w, const float* __restrict__ ln_slots_b,
        const float* __restrict__ ln_in_w, const float* __restrict__ ln_in_b,
        float* __restrict__ out, int last) {
    __shared__ float upd[64], prev[64], giv[192], ghv[192],
                     act[64], mln[64], h1[128], red[8];
    int bs = blockIdx.x;
    int tid = threadIdx.x;

    if (tid < 64) {
        float invden = __fdividef(1.f, g_den[bs]);
        upd[tid] = fmaf(ln_in_w[tid]*invden, g_u[bs*64 + tid] - g_c2[bs],
                        ln_in_b[tid]);
        prev[tid] = g_slots[bs*64 + tid];
    }
    __syncthreads();

    // gi = upd@C^T + b_ih ; gh = prev@W_hh^T + b_hh  (1 output per thread)
    {
        float ai = b_ih[tid], ah = b_hh[tid];
        #pragma unroll 16
        for (int e = 0; e < 64; e++) {
            ai = fmaf(upd[e],  g_CT[e*192 + tid],   ai);
            ah = fmaf(prev[e], g_WHHT[e*192 + tid], ah);
        }
        giv[tid] = ai; ghv[tid] = ah;
    }
    __syncthreads();

    // GRU + LN partials
    if (tid < 64) {
        float r = 1.f/(1.f + __expf(-(giv[tid]     + ghv[tid])));
        float z = 1.f/(1.f + __expf(-(giv[64+tid]  + ghv[64+tid])));
        float n = tanhf(fmaf(r, ghv[128+tid], giv[128+tid]));
        float v = (1.f - z)*n + z*prev[tid];
        act[tid] = v;
        float sum = v, sq = v*v;
        #pragma unroll
        for (int o = 16; o; o >>= 1) {
            sum += __shfl_xor_sync(0xffffffffu, sum, o);
            sq  += __shfl_xor_sync(0xffffffffu, sq,  o);
        }
        if ((tid & 31) == 0) { red[(tid>>5)*2] = sum; red[(tid>>5)*2+1] = sq; }
    }
    __syncthreads();

    if (tid < 64) {
        float sum = red[0] + red[2], sq = red[1] + red[3];
        float m = sum * (1.f/64.f);
        float var = sq * (1.f/64.f) - m*m;
        float r = rsqrtf(var + LN_EPS);
        mln[tid] = (act[tid] - m)*r*ln_mlp_w[tid] + ln_mlp_b[tid];
    }
    __syncthreads();

    if (tid < 128) {
        float acc = b1[tid];
        #pragma unroll 16
        for (int e = 0; e < 64; e++)
            acc = fmaf(mln[e], g_W1T[e*128 + tid], acc);
        h1[tid] = fmaxf(acc, 0.f);
    }
    __syncthreads();

    float res = 0.f;
    if (tid < 64) {
        float acc = b2[tid];
        #pragma unroll 16
        for (int j = 0; j < 128; j++)
            acc = fmaf(h1[j], g_W2T[j*64 + tid], acc);
        res = act[tid] + acc;
        g_slots[bs*64 + tid] = res;
        if (last) out[bs*64 + tid] = res;
    }
    if (last) return;
    __syncthreads();

    // next-iteration prep: LN(res) -> qt -> qw/sw/sb ; zero accumulators
    if (tid < 64) {
        float sum = res, sq = res*res;
        #pragma unroll
        for (int o = 16; o; o >>= 1) {
            sum += __shfl_xor_sync(0xffffffffu, sum, o);
            sq  += __shfl_xor_sync(0xffffffffu, sq,  o);
        }
        if ((tid & 31) == 0) { red[(tid>>5)*2] = sum; red[(tid>>5)*2+1] = sq; }
        g_u[bs*64 + tid] = 0.f;
    }
    if (tid == 0) { g_den[bs] = 0.f; g_c2[bs] = 0.f; }
    __syncthreads();

    if (tid < 64) {
        float sum = red[0] + red[2], sq = red[1] + red[3];
        float m = sum * (1.f/64.f);
        float var = sq * (1.f/64.f) - m*m;
        float r = rsqrtf(var + LN_EPS);
        mln[tid] = (res - m)*r*ln_slots_w[tid] + ln_slots_b[tid];   // reuse mln as sn
    }
    __syncthreads();

    if (tid < 64) {
        float acc = 0.f;
        #pragma unroll 16
        for (int e = 0; e < 64; e++)
            acc = fmaf(mln[e], g_M[e*64 + tid], acc);
        g_qt[bs*64 + tid] = acc * ln_in_w[tid];
        float pa = acc * ln_in_w[tid];
        float pb = acc * ln_in_b[tid];
        #pragma unroll
        for (int o = 16; o; o >>= 1) {
            pa += __shfl_xor_sync(0xffffffffu, pa, o);
            pb += __shfl_xor_sync(0xffffffffu, pb, o);
        }
        if ((tid & 31) == 0) { red[(tid>>5)*2] = pa; red[(tid>>5)*2+1] = pb; }
    }
    __syncthreads();
    if (tid == 0) {
        g_qsc[bs*2 + 0] = red[0] + red[2];
        g_qsc[bs*2 + 1] = red[1] + red[3];
    }
}

// ---------------------------------------------------------------------------
extern "C" void kernel_launch(void* const* d_in, const int* in_sizes, int n_in,
                              void* d_out, int out_size) {
    const float* inputs     = (const float*)d_in[0];
    const float* noise      = (const float*)d_in[1];
    const float* ln_in_w    = (const float*)d_in[2];
    const float* ln_in_b    = (const float*)d_in[3];
    const float* ln_slots_w = (const float*)d_in[4];
    const float* ln_slots_b = (const float*)d_in[5];
    const float* ln_mlp_w   = (const float*)d_in[6];
    const float* ln_mlp_b   = (const float*)d_in[7];
    const float* mu         = (const float*)d_in[8];
    const float* logsig     = (const float*)d_in[9];
    const float* Wq         = (const float*)d_in[10];
    const float* Wk         = (const float*)d_in[11];
    const float* Wv         = (const float*)d_in[12];
    const float* W_ih       = (const float*)d_in[13];
    const float* W_hh       = (const float*)d_in[14];
    const float* b_ih       = (const float*)d_in[15];
    const float* b_hh       = (const float*)d_in[16];
    const float* W1         = (const float*)d_in[17];
    const float* b1         = (const float*)d_in[18];
    const float* W2         = (const float*)d_in[19];
    const float* b2         = (const float*)d_in[20];
    float* out = (float*)d_out;

    cudaFuncSetAttribute(k_attn, cudaFuncAttributeMaxDynamicSharedMemorySize,
                         AT_TOT*4);

    k_init_slots<<<(BB*SS*DD + 255)/256, 256>>>(noise, mu, logsig);
    k_precomp<<<176, 256>>>(Wq, Wk, W_ih, Wv, W_hh, W1, W2);
    k_q0<<<BB, 256>>>(ln_slots_w, ln_slots_b, ln_in_w, ln_in_b);
    for (int it = 0; it < NUM_ITERS; it++) {
        dim3 grid(NN/128, BB);
        k_attn<<<grid, 128, AT_TOT*4>>>(inputs);
        k_finalize<<<BB*SS, 192>>>(b_ih, b_hh, b1, b2,
                                   ln_mlp_w, ln_mlp_b, ln_slots_w, ln_slots_b,
                                   ln_in_w, ln_in_b,
                                   out, it == NUM_ITERS - 1 ? 1 : 0);
    }
}